// round 14
// baseline (speedup 1.0000x reference)
#include <cuda_runtime.h>

#define B_      16
#define CL_     512
#define N_      3136
#define NV_     (N_ / 4)        // 784 float4 per row
#define V4T     64              // float4 columns per tile
#define TILES_R 13              // ceil(784 / 64)
#define NCHUNK  4               // c-chunks across blocks
#define CCHUNK  (CL_ / NCHUNK)  // 128 c per chunk
#define CSUB    (CCHUNK / 4)    // 32 c per intra-block group
#define NPART   (NCHUNK * TILES_R)  // 52 blocks (= t-partials) per batch

// Scratch (__device__ globals — allocation-free rule; zero-initialized)
__device__ float4 d_g4p[NCHUNK * B_ * NV_];   // per-chunk partial g (~800 KB)
__device__ float  d_part[B_ * NPART];         // per-(chunk,tile) partial sums of t
__device__ int    d_done[B_];                 // per-batch phase-1 arrival counter
__device__ int    d_exit[B_];                 // per-batch exit ticket counter

// Fused kernel: grid (13, 16, 4) x 256 threads, ONE wave (832 <= 148*6=888).
// Phase 1: R5-identical reduce. Spin until own batch complete. Phase 2: fold g
// for own 64 columns + mt, write own out region (128 c x 64 n4).
__global__ __launch_bounds__(256, 6) void fused_kernel(
    const float* __restrict__ x,
    const float* __restrict__ theta_w,
    const float* __restrict__ g_w,
    const float* __restrict__ h_w,
    const float* __restrict__ h_b,
    float* __restrict__ out)
{
    __shared__ float  s_tw[CCHUNK];
    __shared__ float  s_gw[CCHUNK];
    __shared__ float4 s_g[256];
    __shared__ float  s_warp[8];
    __shared__ float4 s_gf[V4T];     // folded g for this block's columns
    __shared__ float  s_ts[NPART];   // t partials for this batch
    __shared__ float  s_mt;

    const int tile  = blockIdx.x;
    const int b     = blockIdx.y;
    const int chunk = blockIdx.z;
    const int gr    = threadIdx.x >> 6;          // 0..3
    const int ln    = threadIdx.x & 63;          // 0..63
    const int n4    = tile * V4T + ln;
    const bool valid = (n4 < NV_);
    const int cbase = chunk * CCHUNK;

    if (threadIdx.x < CCHUNK) {
        s_tw[threadIdx.x] = theta_w[cbase + threadIdx.x];
        s_gw[threadIdx.x] = g_w[cbase + threadIdx.x];
    }
    __syncthreads();

    const float4* x4 = reinterpret_cast<const float4*>(x) + (size_t)b * CL_ * NV_;

    // ---------------- Phase 1: reduce (R5-identical) ----------------
    float  t  = 0.0f;
    float4 g4 = make_float4(0.f, 0.f, 0.f, 0.f);

    if (valid) {
        const int cl0 = gr * CSUB;
        const float4* xp = x4 + (size_t)(cbase + cl0) * NV_ + n4;
        #pragma unroll 8
        for (int c = 0; c < CSUB; c++) {
            float4 v  = __ldg(xp + (size_t)c * NV_);
            float  tw = s_tw[cl0 + c];
            float  gw = s_gw[cl0 + c];
            t = fmaf((v.x + v.y) + (v.z + v.w), tw, t);
            g4.x = fmaf(v.x, gw, g4.x);
            g4.y = fmaf(v.y, gw, g4.y);
            g4.z = fmaf(v.z, gw, g4.z);
            g4.w = fmaf(v.w, gw, g4.w);
        }
    }

    s_g[threadIdx.x] = g4;
    __syncthreads();
    if (threadIdx.x < V4T && valid) {
        float4 a  = s_g[threadIdx.x];
        float4 bb = s_g[threadIdx.x + 64];
        float4 cc = s_g[threadIdx.x + 128];
        float4 dd = s_g[threadIdx.x + 192];
        float4 o;
        o.x = (a.x + bb.x) + (cc.x + dd.x);
        o.y = (a.y + bb.y) + (cc.y + dd.y);
        o.z = (a.z + bb.z) + (cc.z + dd.z);
        o.w = (a.w + bb.w) + (cc.w + dd.w);
        d_g4p[(chunk * B_ + b) * NV_ + n4] = o;
    }

    #pragma unroll
    for (int off = 16; off > 0; off >>= 1)
        t += __shfl_down_sync(0xFFFFFFFFu, t, off);
    if ((threadIdx.x & 31) == 0) s_warp[threadIdx.x >> 5] = t;
    __syncthreads();
    if (threadIdx.x == 0) {
        float s = 0.0f;
        #pragma unroll
        for (int w = 0; w < 8; w++) s += s_warp[w];
        d_part[b * NPART + chunk * TILES_R + tile] = s;
    }

    // ---------------- Barrier: wait for own batch's 52 blocks ----------------
    __threadfence();                       // publish d_g4p / d_part (all threads)
    __syncthreads();
    if (threadIdx.x == 0) {
        atomicAdd(&d_done[b], 1);
        while (*((volatile int*)&d_done[b]) < NPART) __nanosleep(64);
    }
    __syncthreads();
    __threadfence();                       // acquire side

    // ---------------- Fold g (own columns) + mt ----------------
    if (threadIdx.x < V4T && valid) {
        const int gi = b * NV_ + n4;
        const int stride = B_ * NV_;
        float4 p0 = d_g4p[gi];
        float4 p1 = d_g4p[gi + stride];
        float4 p2 = d_g4p[gi + 2 * stride];
        float4 p3 = d_g4p[gi + 3 * stride];
        float4 o;
        o.x = (p0.x + p1.x) + (p2.x + p3.x);
        o.y = (p0.y + p1.y) + (p2.y + p3.y);
        o.z = (p0.z + p1.z) + (p2.z + p3.z);
        o.w = (p0.w + p1.w) + (p2.w + p3.w);
        s_gf[threadIdx.x] = o;
    }
    if (threadIdx.x >= 64 && threadIdx.x < 64 + NPART)
        s_ts[threadIdx.x - 64] = d_part[b * NPART + (threadIdx.x - 64)];
    __syncthreads();
    if (threadIdx.x == 0) {
        float s = 0.0f;
        #pragma unroll
        for (int k = 0; k < NPART; k++) s += s_ts[k];
        s_mt = s * (1.0f / (float)N_);
    }
    __syncthreads();
    const float mt = s_mt;

    // ---------------- Phase 2: write own out region ----------------
    // rows c = cbase..cbase+127, cols n4 = tile*64..tile*64+63 (tail-guarded)
    {
        const float4* xr  = reinterpret_cast<const float4*>(x);
        float4*       outr = reinterpret_cast<float4*>(out);
        #pragma unroll 4
        for (int idx = threadIdx.x; idx < CCHUNK * V4T; idx += 256) {
            const int col = idx & 63;            // warp-contiguous
            const int r   = idx >> 6;
            const int nc  = tile * V4T + col;
            if (nc < NV_) {
                const int   cg  = cbase + r;
                const float hwc = h_w[cg] * mt;       // warp-uniform -> L1 hit
                const float hbc = h_b[cg];
                const size_t off = ((size_t)b * CL_ + cg) * NV_ + nc;
                const float4 xv = __ldcs(xr + off);   // last use of x
                const float4 gg = s_gf[col];
                float4 o;
                o.x = fmaf(gg.x, hwc, xv.x) + hbc;
                o.y = fmaf(gg.y, hwc, xv.y) + hbc;
                o.z = fmaf(gg.z, hwc, xv.z) + hbc;
                o.w = fmaf(gg.w, hwc, xv.w) + hbc;
                __stcs(outr + off, o);                // streaming store
            }
        }
    }

    // ---------------- Exit tickets: last block of batch resets counters ----------------
    __syncthreads();
    if (threadIdx.x == 0) {
        int tkt = atomicAdd(&d_exit[b], 1);
        if (tkt == NPART - 1) {
            d_done[b] = 0;                // safe: all 52 passed the spin + phase 2
            d_exit[b] = 0;
            __threadfence();
        }
    }
}

extern "C" void kernel_launch(void* const* d_in, const int* in_sizes, int n_in,
                              void* d_out, int out_size)
{
    const float* x       = (const float*)d_in[0];
    const float* theta_w = (const float*)d_in[1];
    const float* g_w     = (const float*)d_in[2];
    const float* h_w     = (const float*)d_in[3];
    const float* h_b     = (const float*)d_in[4];
    float*       out     = (float*)d_out;

    dim3 grid(TILES_R, B_, NCHUNK);        // 13 x 16 x 4 = 832 blocks, one wave
    fused_kernel<<<grid, 256>>>(x, theta_w, g_w, h_w, h_b, out);
}

// round 15
// speedup vs baseline: 1.0811x; 1.0811x over previous
#include <cuda_runtime.h>
#include <cstdint>

#define B_      16
#define CL_     512
#define N_      3136
#define NV_     (N_ / 4)        // 784 float4 per row
#define V4T     56              // float4 columns per tile: 784 = 14 * 56 (no tail)
#define TILES_R 14
#define TPB_R   224             // 4 c-groups x 56 lanes
#define NCHUNK  4               // c-chunks across blocks
#define CCHUNK  (CL_ / NCHUNK)  // 128 c per chunk
#define ROWS_ST 8               // c-rows per pipeline stage
#define NSTAGE  (CCHUNK / ROWS_ST)   // 16 stages
#define PIPE    4               // pipeline depth (buffers)
#define STG_V4  (ROWS_ST * V4T)      // 448 float4 = 7168 B per stage
#define NPART   (NCHUNK * TILES_R)   // 56 t-partials per b

// Scratch (__device__ globals — allocation-free rule)
__device__ float4 d_g4p[NCHUNK * B_ * NV_];   // per-chunk partial g (~800 KB)
__device__ float4 d_g4[B_ * NV_];             // folded g (~200 KB)
__device__ float  d_part[B_ * NPART];         // per-(chunk,tile) partial sums of t
__device__ float  d_mt[B_];                   // mean(t) per batch

__device__ __forceinline__ void cp_async16(uint32_t saddr, const float4* g) {
    asm volatile("cp.async.cg.shared.global [%0], [%1], 16;"
                 :: "r"(saddr), "l"(g));
}

// Pass 1: cp.async 4-stage pipeline. grid (14,16,4) x 224 threads.
// MLP comes from async-copy depth (3 stages x 7 KB in flight per block),
// not from registers — breaks the ptxas load/use re-fusion that capped R5-R11.
__global__ __launch_bounds__(TPB_R) void reduce_kernel(
    const float* __restrict__ x,
    const float* __restrict__ theta_w,
    const float* __restrict__ g_w)
{
    __shared__ float4 s_buf[PIPE][STG_V4];    // 28672 B
    __shared__ float  s_tw[CCHUNK];
    __shared__ float  s_gw[CCHUNK];
    __shared__ float4 s_g[TPB_R];
    __shared__ float  s_warp[TPB_R / 32];

    const int tile  = blockIdx.x;
    const int b     = blockIdx.y;
    const int chunk = blockIdx.z;
    const int tid   = threadIdx.x;
    const int gr    = tid / V4T;              // 0..3
    const int ln    = tid % V4T;              // 0..55
    const int cbase = chunk * CCHUNK;

    if (tid < CCHUNK) {
        s_tw[tid] = theta_w[cbase + tid];
        s_gw[tid] = g_w[cbase + tid];
    }
    // (first in-loop __syncthreads orders these before first compute)

    // block's gmem tile origin: rows cbase.., columns tile*56..
    const float4* xg = reinterpret_cast<const float4*>(x)
                     + (size_t)b * CL_ * NV_ + (size_t)cbase * NV_ + tile * V4T;

    const uint32_t sbase = (uint32_t)__cvta_generic_to_shared(&s_buf[0][0]);

    // Each thread copies stage elements e = tid (row gr, col ln) and
    // e = tid+224 (row gr+4, col ln). 448 elems/stage, 2 cp.async/thread.
    auto issue = [&](int s) {
        const uint32_t sb = sbase + (uint32_t)(s % PIPE) * (STG_V4 * 16);
        const float4*  gs = xg + (size_t)(s * ROWS_ST) * NV_;
        cp_async16(sb + (uint32_t)tid * 16,            gs + (size_t)gr * NV_ + ln);
        cp_async16(sb + (uint32_t)(tid + TPB_R) * 16,  gs + (size_t)(gr + 4) * NV_ + ln);
        asm volatile("cp.async.commit_group;");
    };

    float  t  = 0.0f;
    float4 g4 = make_float4(0.f, 0.f, 0.f, 0.f);

    #pragma unroll
    for (int s = 0; s < PIPE - 1; s++) issue(s);      // prologue: stages 0..2

    for (int s = 0; s < NSTAGE; s++) {
        if (s + PIPE - 1 < NSTAGE) issue(s + PIPE - 1);
        else asm volatile("cp.async.commit_group;");  // dummy keeps group count fixed
        asm volatile("cp.async.wait_group %0;" :: "n"(PIPE - 1));
        __syncthreads();                              // stage s visible to all

        const float4* buf = s_buf[s % PIPE];
        #pragma unroll
        for (int rr = 0; rr < 2; rr++) {              // group gr computes rows gr*2+rr
            const int   r  = gr * 2 + rr;
            const float4 v = buf[r * V4T + ln];
            const float tw = s_tw[s * ROWS_ST + r];
            const float gw = s_gw[s * ROWS_ST + r];
            t = fmaf((v.x + v.y) + (v.z + v.w), tw, t);
            g4.x = fmaf(v.x, gw, g4.x);
            g4.y = fmaf(v.y, gw, g4.y);
            g4.z = fmaf(v.z, gw, g4.z);
            g4.w = fmaf(v.w, gw, g4.w);
        }
        __syncthreads();                              // buffer safe to overwrite
    }

    // combine g across the 4 intra-block c-groups
    s_g[tid] = g4;
    __syncthreads();
    if (tid < V4T) {
        float4 a  = s_g[tid];
        float4 bb = s_g[tid + V4T];
        float4 cc = s_g[tid + 2 * V4T];
        float4 dd = s_g[tid + 3 * V4T];
        float4 o;
        o.x = (a.x + bb.x) + (cc.x + dd.x);
        o.y = (a.y + bb.y) + (cc.y + dd.y);
        o.z = (a.z + bb.z) + (cc.z + dd.z);
        o.w = (a.w + bb.w) + (cc.w + dd.w);
        d_g4p[(chunk * B_ + b) * NV_ + tile * V4T + tid] = o;
    }

    // reduce t across the block -> one partial
    #pragma unroll
    for (int off = 16; off > 0; off >>= 1)
        t += __shfl_down_sync(0xFFFFFFFFu, t, off);
    if ((tid & 31) == 0) s_warp[tid >> 5] = t;
    __syncthreads();
    if (tid == 0) {
        float s = 0.0f;
        #pragma unroll
        for (int w = 0; w < TPB_R / 32; w++) s += s_warp[w];
        d_part[b * NPART + chunk * TILES_R + tile] = s;
    }
}

// Fold: collapse 4 per-chunk g partials into d_g4, and finish the t mean.
__global__ __launch_bounds__(256) void fold_kernel()
{
    const int i = blockIdx.x * blockDim.x + threadIdx.x;   // 0 .. B_*NV_-1
    const int stride = B_ * NV_;

    float4 p0 = d_g4p[i];
    float4 p1 = d_g4p[i + stride];
    float4 p2 = d_g4p[i + 2 * stride];
    float4 p3 = d_g4p[i + 3 * stride];
    float4 o;
    o.x = (p0.x + p1.x) + (p2.x + p3.x);
    o.y = (p0.y + p1.y) + (p2.y + p3.y);
    o.z = (p0.z + p1.z) + (p2.z + p3.z);
    o.w = (p0.w + p1.w) + (p2.w + p3.w);
    d_g4[i] = o;

    if (blockIdx.x == 0 && threadIdx.x < B_) {
        float s = 0.0f;
        #pragma unroll
        for (int k = 0; k < NPART; k++) s += d_part[threadIdx.x * NPART + k];
        d_mt[threadIdx.x] = s * (1.0f / (float)N_);
    }
}

// Pass 2 (R5 measured-best): 2 loads + 1 store per thread. Reverse traversal
// for L2 reuse of x; __stcs streaming store.
__global__ __launch_bounds__(256) void out_kernel(
    const float* __restrict__ x,
    const float* __restrict__ h_w,
    const float* __restrict__ h_b,
    float* __restrict__ out)
{
    const int total = B_ * CL_ * NV_;                      // 6,422,528 vec4
    const int v = total - 1 - (blockIdx.x * blockDim.x + threadIdx.x);

    const int n4  = v % NV_;
    const int row = v / NV_;          // row = b*CL + c
    const int c   = row % CL_;
    const int b   = row / CL_;

    const float mt  = __ldg(&d_mt[b]);      // uniform per block -> L1 hit
    const float hwc = h_w[c] * mt;
    const float hbc = h_b[c];

    const float4 g4 = d_g4[b * NV_ + n4];
    const float4 x4 = __ldcs(reinterpret_cast<const float4*>(x) + v);   // last use of x

    float4 o;
    o.x = fmaf(g4.x, hwc, x4.x) + hbc;
    o.y = fmaf(g4.y, hwc, x4.y) + hbc;
    o.z = fmaf(g4.z, hwc, x4.z) + hbc;
    o.w = fmaf(g4.w, hwc, x4.w) + hbc;

    __stcs(reinterpret_cast<float4*>(out) + v, o);          // streaming store
}

extern "C" void kernel_launch(void* const* d_in, const int* in_sizes, int n_in,
                              void* d_out, int out_size)
{
    const float* x       = (const float*)d_in[0];
    const float* theta_w = (const float*)d_in[1];
    const float* g_w     = (const float*)d_in[2];
    const float* h_w     = (const float*)d_in[3];
    const float* h_b     = (const float*)d_in[4];
    float*       out     = (float*)d_out;

    dim3 grid1(TILES_R, B_, NCHUNK);       // 14 x 16 x 4 = 896 blocks, 224 threads
    reduce_kernel<<<grid1, TPB_R>>>(x, theta_w, g_w);

    fold_kernel<<<(B_ * NV_) / 256, 256>>>();   // 49 blocks

    const int total_vec4 = B_ * CL_ * NV_; // 6,422,528
    out_kernel<<<total_vec4 / 256, 256>>>(x, h_w, h_b, out);
}